// round 1
// baseline (speedup 1.0000x reference)
#include <cuda_runtime.h>
#include <cstdint>

#define FULL_MASK 0xffffffffu

__device__ __forceinline__ uint32_t f2tf(float f) {
    uint32_t u;
    asm("cvt.rna.tf32.f32 %0, %1;" : "=r"(u) : "f"(f));
    return u;
}

__device__ __forceinline__ void mma_tf32(float& c0, float& c1, float& c2, float& c3,
                                         uint32_t a0, uint32_t a1, uint32_t a2, uint32_t a3,
                                         uint32_t b0, uint32_t b1) {
    asm volatile("mma.sync.aligned.m16n8k8.row.col.f32.tf32.tf32.f32 "
                 "{%0,%1,%2,%3}, {%4,%5,%6,%7}, {%8,%9}, {%0,%1,%2,%3};"
                 : "+f"(c0), "+f"(c1), "+f"(c2), "+f"(c3)
                 : "r"(a0), "r"(a1), "r"(a2), "r"(a3), "r"(b0), "r"(b1));
}

// Scratch (allocation-free rule: __device__ globals)
__device__ float g_q[4096 * 1024];
__device__ float g_k[4096 * 1024];
__device__ float g_v[4096 * 1024];
__device__ float g_ctx[4096 * 1024];

// ---------------------------------------------------------------------------
// TF32 GEMM: C[M,N] = A[M,K] @ W[K,N] (+bias). BM=128 BN=128 BK=16, 256 thr.
// 8 warps in 2x4; each warp 64x32 via 4x4 m16n8k8 tiles.
// ---------------------------------------------------------------------------
template <bool BIAS>
__device__ __forceinline__ void gemm_body(const float* __restrict__ A,
                                          const float* __restrict__ W,
                                          const float* __restrict__ bias,
                                          float* __restrict__ C,
                                          int M, int N, int K) {
    __shared__ uint32_t As[128][20];   // [m][k], pad 16->20: conflict-free frag loads
    __shared__ uint32_t Bs[16][136];   // [k][n], pad 128->136: conflict-free

    const int tid  = threadIdx.x;
    const int lane = tid & 31;
    const int wid  = tid >> 5;
    const int wm   = wid >> 2;   // 0..1
    const int wn   = wid & 3;    // 0..3
    const int row0 = blockIdx.y * 128;
    const int col0 = blockIdx.x * 128;

    float acc[4][4][4];
#pragma unroll
    for (int mt = 0; mt < 4; mt++)
#pragma unroll
        for (int nt = 0; nt < 4; nt++)
#pragma unroll
            for (int r = 0; r < 4; r++) acc[mt][nt][r] = 0.f;

    const int nK = K >> 4;
    for (int kt = 0; kt < nK; ++kt) {
        __syncthreads();
        // A tile: 128 rows x 16 cols = 512 float4 loads
#pragma unroll
        for (int l = 0; l < 2; l++) {
            int e  = l * 256 + tid;
            int r  = e >> 2;
            int c4 = (e & 3) << 2;
            float4 v = *reinterpret_cast<const float4*>(
                &A[(size_t)(row0 + r) * K + (size_t)kt * 16 + c4]);
            uint4 u = make_uint4(f2tf(v.x), f2tf(v.y), f2tf(v.z), f2tf(v.w));
            *reinterpret_cast<uint4*>(&As[r][c4]) = u;
        }
        // B tile: 16 rows x 128 cols
#pragma unroll
        for (int l = 0; l < 2; l++) {
            int e  = l * 256 + tid;
            int r  = e >> 5;
            int c4 = (e & 31) << 2;
            float4 v = *reinterpret_cast<const float4*>(
                &W[(size_t)(kt * 16 + r) * N + col0 + c4]);
            uint4 u = make_uint4(f2tf(v.x), f2tf(v.y), f2tf(v.z), f2tf(v.w));
            *reinterpret_cast<uint4*>(&Bs[r][c4]) = u;
        }
        __syncthreads();

#pragma unroll
        for (int ks = 0; ks < 16; ks += 8) {
            uint32_t afr[4][4];
#pragma unroll
            for (int mt = 0; mt < 4; mt++) {
                int r = wm * 64 + mt * 16 + (lane >> 2);
                int k = ks + (lane & 3);
                afr[mt][0] = As[r][k];
                afr[mt][1] = As[r + 8][k];
                afr[mt][2] = As[r][k + 4];
                afr[mt][3] = As[r + 8][k + 4];
            }
            uint32_t bfr[4][2];
#pragma unroll
            for (int nt = 0; nt < 4; nt++) {
                int c = wn * 32 + nt * 8 + (lane >> 2);
                int k = ks + (lane & 3);
                bfr[nt][0] = Bs[k][c];
                bfr[nt][1] = Bs[k + 4][c];
            }
#pragma unroll
            for (int mt = 0; mt < 4; mt++)
#pragma unroll
                for (int nt = 0; nt < 4; nt++)
                    mma_tf32(acc[mt][nt][0], acc[mt][nt][1], acc[mt][nt][2], acc[mt][nt][3],
                             afr[mt][0], afr[mt][1], afr[mt][2], afr[mt][3],
                             bfr[nt][0], bfr[nt][1]);
        }
    }

#pragma unroll
    for (int mt = 0; mt < 4; mt++) {
        int rl = row0 + wm * 64 + mt * 16 + (lane >> 2);
        int rh = rl + 8;
#pragma unroll
        for (int nt = 0; nt < 4; nt++) {
            int c = col0 + wn * 32 + nt * 8 + 2 * (lane & 3);
            float b0v = BIAS ? bias[c] : 0.f;
            float b1v = BIAS ? bias[c + 1] : 0.f;
            float2 lo = make_float2(acc[mt][nt][0] + b0v, acc[mt][nt][1] + b1v);
            float2 hi = make_float2(acc[mt][nt][2] + b0v, acc[mt][nt][3] + b1v);
            *reinterpret_cast<float2*>(&C[(size_t)rl * N + c]) = lo;
            *reinterpret_cast<float2*>(&C[(size_t)rh * N + c]) = hi;
        }
    }
}

__global__ void __launch_bounds__(256) qkv_gemm_kernel(const float* __restrict__ x,
                                                       const float* __restrict__ Wq,
                                                       const float* __restrict__ Wk,
                                                       const float* __restrict__ Wv) {
    int z = blockIdx.z;
    const float* W = (z == 0) ? Wq : (z == 1) ? Wk : Wv;
    float* out = (z == 0) ? g_q : (z == 1) ? g_k : g_v;
    gemm_body<false>(x, W, nullptr, out, 4096, 1024, 1024);
}

__global__ void __launch_bounds__(256) out_gemm_kernel(const float* __restrict__ Wo,
                                                       const float* __restrict__ bo,
                                                       float* __restrict__ out) {
    gemm_body<true>(g_ctx, Wo, bo, out, 4096, 1024, 1024);
}

// ---------------------------------------------------------------------------
// Causal flash attention. Block = 128 thr (4 warps), 64 q-rows/block, 64 k/iter.
// grid = (32 q-tiles, 32 b*h). Q frags register-resident (scale 1/8 folded in).
// ---------------------------------------------------------------------------
__global__ void __launch_bounds__(128) attn_kernel() {
    __shared__ uint32_t sK[64][68];   // [key][d] tf32, pad 64->68: conflict-free
    __shared__ uint32_t sV[64][68];   // [key][d]

    const int tid  = threadIdx.x;
    const int lane = tid & 31;
    const int w    = tid >> 5;
    const int qt   = blockIdx.x;
    const int bh   = blockIdx.y;
    const int b    = bh >> 4;
    const int h    = bh & 15;
    const size_t seq_base = (size_t)b * 2048;
    const int hd   = h << 6;
    const float LOG2E = 1.4426950408889634f;

    // Preload Q fragments (16 rows per warp, D=64 -> 8 k-steps), scaled by 1/8
    uint32_t qa[8][4];
    {
        int r_lo = qt * 64 + w * 16 + (lane >> 2);
        const float* Ql = g_q + (seq_base + r_lo) * 1024 + hd;
        const float* Qh = Ql + 8 * 1024;
#pragma unroll
        for (int t = 0; t < 8; t++) {
            int d0 = t * 8 + (lane & 3);
            qa[t][0] = f2tf(0.125f * Ql[d0]);
            qa[t][1] = f2tf(0.125f * Qh[d0]);
            qa[t][2] = f2tf(0.125f * Ql[d0 + 4]);
            qa[t][3] = f2tf(0.125f * Qh[d0 + 4]);
        }
    }

    float oacc[8][4];
#pragma unroll
    for (int n = 0; n < 8; n++)
#pragma unroll
        for (int r = 0; r < 4; r++) oacc[n][r] = 0.f;
    float m_lo = -1e30f, m_hi = -1e30f, l_lo = 0.f, l_hi = 0.f;

    for (int kt = 0; kt <= qt; ++kt) {
        __syncthreads();   // previous iter's smem reads done
        // Load K and V tiles (64x64 fp32 each), convert to tf32
#pragma unroll
        for (int ls = 0; ls < 8; ++ls) {
            int e  = ls * 128 + tid;          // 0..1023 float4s
            int r  = e >> 4;
            int c4 = (e & 15) << 2;
            size_t ga = (seq_base + (size_t)kt * 64 + r) * 1024 + hd + c4;
            float4 kv = *reinterpret_cast<const float4*>(&g_k[ga]);
            float4 vv = *reinterpret_cast<const float4*>(&g_v[ga]);
            *reinterpret_cast<uint4*>(&sK[r][c4]) =
                make_uint4(f2tf(kv.x), f2tf(kv.y), f2tf(kv.z), f2tf(kv.w));
            *reinterpret_cast<uint4*>(&sV[r][c4]) =
                make_uint4(f2tf(vv.x), f2tf(vv.y), f2tf(vv.z), f2tf(vv.w));
        }
        __syncthreads();

        // S = (Q/8) @ K^T  -- per warp: 16 rows x 64 keys
        float sacc[8][4];
#pragma unroll
        for (int j = 0; j < 8; j++)
#pragma unroll
            for (int r = 0; r < 4; r++) sacc[j][r] = 0.f;
#pragma unroll
        for (int j = 0; j < 8; j++) {
#pragma unroll
            for (int t = 0; t < 8; t++) {
                uint32_t b0 = sK[j * 8 + (lane >> 2)][t * 8 + (lane & 3)];
                uint32_t b1 = sK[j * 8 + (lane >> 2)][t * 8 + (lane & 3) + 4];
                mma_tf32(sacc[j][0], sacc[j][1], sacc[j][2], sacc[j][3],
                         qa[t][0], qa[t][1], qa[t][2], qa[t][3], b0, b1);
            }
        }

        // Causal mask (only the diagonal tile needs it)
        if (kt == qt) {
            int gq_lo = qt * 64 + w * 16 + (lane >> 2);
            int gq_hi = gq_lo + 8;
#pragma unroll
            for (int j = 0; j < 8; j++) {
                int gk = kt * 64 + j * 8 + 2 * (lane & 3);
                if (gk > gq_lo)     sacc[j][0] = -1e30f;
                if (gk + 1 > gq_lo) sacc[j][1] = -1e30f;
                if (gk > gq_hi)     sacc[j][2] = -1e30f;
                if (gk + 1 > gq_hi) sacc[j][3] = -1e30f;
            }
        }

        // Online softmax (rows: lo = lane>>2, hi = +8; quad reduce over lane%4)
        float mx_lo = -1e30f, mx_hi = -1e30f;
#pragma unroll
        for (int j = 0; j < 8; j++) {
            mx_lo = fmaxf(mx_lo, fmaxf(sacc[j][0], sacc[j][1]));
            mx_hi = fmaxf(mx_hi, fmaxf(sacc[j][2], sacc[j][3]));
        }
        mx_lo = fmaxf(mx_lo, __shfl_xor_sync(FULL_MASK, mx_lo, 1));
        mx_lo = fmaxf(mx_lo, __shfl_xor_sync(FULL_MASK, mx_lo, 2));
        mx_hi = fmaxf(mx_hi, __shfl_xor_sync(FULL_MASK, mx_hi, 1));
        mx_hi = fmaxf(mx_hi, __shfl_xor_sync(FULL_MASK, mx_hi, 2));
        float mn_lo = fmaxf(m_lo, mx_lo);
        float mn_hi = fmaxf(m_hi, mx_hi);
        float al_lo = exp2f((m_lo - mn_lo) * LOG2E);
        float al_hi = exp2f((m_hi - mn_hi) * LOG2E);
        m_lo = mn_lo; m_hi = mn_hi;

        float s_lo = 0.f, s_hi = 0.f;
#pragma unroll
        for (int j = 0; j < 8; j++) {
            sacc[j][0] = exp2f((sacc[j][0] - m_lo) * LOG2E);
            sacc[j][1] = exp2f((sacc[j][1] - m_lo) * LOG2E);
            sacc[j][2] = exp2f((sacc[j][2] - m_hi) * LOG2E);
            sacc[j][3] = exp2f((sacc[j][3] - m_hi) * LOG2E);
            s_lo += sacc[j][0] + sacc[j][1];
            s_hi += sacc[j][2] + sacc[j][3];
        }
        s_lo += __shfl_xor_sync(FULL_MASK, s_lo, 1);
        s_lo += __shfl_xor_sync(FULL_MASK, s_lo, 2);
        s_hi += __shfl_xor_sync(FULL_MASK, s_hi, 1);
        s_hi += __shfl_xor_sync(FULL_MASK, s_hi, 2);
        l_lo = l_lo * al_lo + s_lo;
        l_hi = l_hi * al_hi + s_hi;

#pragma unroll
        for (int n = 0; n < 8; n++) {
            oacc[n][0] *= al_lo; oacc[n][1] *= al_lo;
            oacc[n][2] *= al_hi; oacc[n][3] *= al_hi;
        }

        // O += P @ V. P (C-layout) -> A-layout via intra-quad shuffles.
        const int c    = lane & 3;
        const int srcA = (lane & ~3) | (c >> 1);
        const int srcB = srcA + 2;
#pragma unroll
        for (int j = 0; j < 8; j++) {
            float y0 = __shfl_sync(FULL_MASK, sacc[j][0], srcA);
            float y1 = __shfl_sync(FULL_MASK, sacc[j][1], srcA);
            float y2 = __shfl_sync(FULL_MASK, sacc[j][2], srcA);
            float y3 = __shfl_sync(FULL_MASK, sacc[j][3], srcA);
            float z0 = __shfl_sync(FULL_MASK, sacc[j][0], srcB);
            float z1 = __shfl_sync(FULL_MASK, sacc[j][1], srcB);
            float z2 = __shfl_sync(FULL_MASK, sacc[j][2], srcB);
            float z3 = __shfl_sync(FULL_MASK, sacc[j][3], srcB);
            uint32_t a0 = f2tf((c & 1) ? y1 : y0);
            uint32_t a1 = f2tf((c & 1) ? y3 : y2);
            uint32_t a2 = f2tf((c & 1) ? z1 : z0);
            uint32_t a3 = f2tf((c & 1) ? z3 : z2);
#pragma unroll
            for (int n = 0; n < 8; n++) {
                uint32_t b0 = sV[j * 8 + (lane & 3)][n * 8 + (lane >> 2)];
                uint32_t b1 = sV[j * 8 + (lane & 3) + 4][n * 8 + (lane >> 2)];
                mma_tf32(oacc[n][0], oacc[n][1], oacc[n][2], oacc[n][3],
                         a0, a1, a2, a3, b0, b1);
            }
        }
    }

    // Normalize and write ctx in [B,S,E] layout
    float inv_lo = 1.f / l_lo;
    float inv_hi = 1.f / l_hi;
    int r_lo = qt * 64 + w * 16 + (lane >> 2);
    float* Cl = g_ctx + (seq_base + r_lo) * 1024 + hd;
    float* Ch = Cl + 8 * 1024;
#pragma unroll
    for (int n = 0; n < 8; n++) {
        int col = n * 8 + 2 * (lane & 3);
        *reinterpret_cast<float2*>(&Cl[col]) =
            make_float2(oacc[n][0] * inv_lo, oacc[n][1] * inv_lo);
        *reinterpret_cast<float2*>(&Ch[col]) =
            make_float2(oacc[n][2] * inv_hi, oacc[n][3] * inv_hi);
    }
}

// ---------------------------------------------------------------------------
extern "C" void kernel_launch(void* const* d_in, const int* in_sizes, int n_in,
                              void* d_out, int out_size) {
    const float* x  = (const float*)d_in[0];
    const float* Wq = (const float*)d_in[1];
    const float* Wk = (const float*)d_in[2];
    const float* Wv = (const float*)d_in[3];
    const float* Wo = (const float*)d_in[4];
    const float* bo = (const float*)d_in[5];
    float* out = (float*)d_out;

    qkv_gemm_kernel<<<dim3(8, 32, 3), 256>>>(x, Wq, Wk, Wv);
    attn_kernel<<<dim3(32, 32), 128>>>();
    out_gemm_kernel<<<dim3(8, 32, 1), 256>>>(Wo, bo, out);
}